// round 4
// baseline (speedup 1.0000x reference)
#include <cuda_runtime.h>
#include <cuda_fp16.h>
#include <cstdint>
#include <cmath>

// Problem constants
#define BATCH 64
#define TSTEPS 512
#define DIM 1024
#define OUTD 1024
#define M_TOTAL (BATCH * TSTEPS)   // 32768
#define NCHUNKS 8                  // N / BN

// Scratch (device globals: no allocations allowed)
__device__ float g_WaS[BATCH * OUTD];            // prev@Wa + Ba
__device__ float g_partial[M_TOTAL * NCHUNKS];   // per-(row, n-chunk) partial Va-dot
__device__ float g_sm[BATCH * TSTEPS];           // softmax weights

// pack two fp32 -> fp16x2 (lo in lower 16 bits)
__device__ __forceinline__ uint32_t pack_f16x2(float lo, float hi) {
    uint32_t r;
    asm("cvt.rn.f16x2.f32 %0, %1, %2;" : "=r"(r) : "f"(hi), "f"(lo));
    return r;
}

__device__ __forceinline__ void mma_f16(float* c, const uint32_t* a, const uint32_t* b) {
    asm("mma.sync.aligned.m16n8k16.row.col.f32.f16.f16.f32 "
        "{%0,%1,%2,%3}, {%4,%5,%6,%7}, {%8,%9}, {%0,%1,%2,%3};"
        : "+f"(c[0]), "+f"(c[1]), "+f"(c[2]), "+f"(c[3])
        : "r"(a[0]), "r"(a[1]), "r"(a[2]), "r"(a[3]), "r"(b[0]), "r"(b[1]));
}

__device__ __forceinline__ void ldsm_x4(uint32_t& r0, uint32_t& r1,
                                        uint32_t& r2, uint32_t& r3, uint32_t addr) {
    asm volatile("ldmatrix.sync.aligned.m8n8.x4.shared.b16 {%0,%1,%2,%3}, [%4];"
                 : "=r"(r0), "=r"(r1), "=r"(r2), "=r"(r3) : "r"(addr));
}

__device__ __forceinline__ uint32_t smem_u32(const void* p) {
    uint32_t a;
    asm("{ .reg .u64 t; cvta.to.shared.u64 t, %1; cvt.u32.u64 %0, t; }"
        : "=r"(a) : "l"(p));
    return a;
}

// ---------------------------------------------------------------------------
// Kernel 1: WaS[b,o] = Ba[o] + sum_k prev[b,k] * Wa[k,o]
// ---------------------------------------------------------------------------
__global__ __launch_bounds__(256) void was_kernel(
    const float* __restrict__ prev, const float* __restrict__ Wa,
    const float* __restrict__ Ba)
{
    int o0 = blockIdx.x * 8;
    int oo = threadIdx.x & 7;
    int bq = threadIdx.x >> 3;

    __shared__ float ps[64][33];
    __shared__ float ws[32][9];

    float acc0 = 0.f, acc1 = 0.f;
    for (int k0 = 0; k0 < OUTD; k0 += 32) {
        #pragma unroll
        for (int j = 0; j < 8; ++j) {
            int e = threadIdx.x + j * 256;
            int bb = e >> 5, kk = e & 31;
            ps[bb][kk] = prev[bb * OUTD + k0 + kk];
        }
        {
            int kk = threadIdx.x >> 3, o = threadIdx.x & 7;
            ws[kk][o] = Wa[(size_t)(k0 + kk) * OUTD + o0 + o];
        }
        __syncthreads();
        #pragma unroll
        for (int kk = 0; kk < 32; ++kk) {
            float w = ws[kk][oo];
            acc0 = fmaf(ps[bq * 2 + 0][kk], w, acc0);
            acc1 = fmaf(ps[bq * 2 + 1][kk], w, acc1);
        }
        __syncthreads();
    }
    float bav = Ba[o0 + oo];
    g_WaS[(bq * 2 + 0) * OUTD + o0 + oo] = acc0 + bav;
    g_WaS[(bq * 2 + 1) * OUTD + o0 + oo] = acc1 + bav;
}

// ---------------------------------------------------------------------------
// Kernel 2: fused GEMM  C = inputs @ Ua  (fp16 mma.sync m16n8k16, fp32 accum)
// epilogue: partial[m, nchunk] = sum_n Va[n] * tanh(C[m,n] + WaS[b,n])
// BM=128, BN=128, BK=32, 256 threads, 8 warps (4M x 2N), warp tile 32x64.
// Fragment loads via ldmatrix:
//   As: [128 rows][20 words], row r = m-row, words 0..15 = (k,k+1) fp16 pairs.
//       banks 20r mod 32 distinct over any 8 consecutive rows -> LDSM conflict-free.
//   Bs: [128 rows][20 words], row = n, words = (k,k+1) pairs (transposed at STS).
// ---------------------------------------------------------------------------
#define BM 128
#define BN 128
#define BK 32
#define NKT (DIM / BK)   // 32
#define AROW_W 20        // words per row incl. padding

__global__ __launch_bounds__(256, 2) void attn_gemm_kernel(
    const float* __restrict__ X,   // [M_TOTAL, DIM]
    const float* __restrict__ Ua,  // [DIM, OUTD]
    const float* __restrict__ Va)  // [OUTD]
{
    __shared__ uint32_t As[2][BM][AROW_W];   // 20480 B
    __shared__ uint32_t Bs[2][BN][AROW_W];   // 20480 B
    __shared__ float sc[2][BM];
    __shared__ float vva[BN];
    __shared__ float wss[BN];

    const int tid = threadIdx.x;
    const int lane = tid & 31;
    const int wid = tid >> 5;
    const int wm = wid & 3;        // warp M index (0..3)
    const int wn = wid >> 2;       // warp N index (0..1)
    const int gid = lane >> 2;     // 0..7
    const int t4  = lane & 3;      // 0..3
    const int n0 = blockIdx.x * BN;
    const int m0 = blockIdx.y * BM;
    const int b  = m0 >> 9;

    // per-thread ldmatrix byte offsets (within one stage)
    const uint32_t As_base = smem_u32(&As[0][0][0]);
    const uint32_t Bs_base = smem_u32(&Bs[0][0][0]);
    const uint32_t offA = (uint32_t)((wm * 32 + (lane & 15)) * (AROW_W * 4)
                                     + ((lane & 16) ? 16 : 0));
    const uint32_t offB = (uint32_t)((wn * 64 + (lane & 7) + ((lane & 16) ? 8 : 0))
                                         * (AROW_W * 4)
                                     + ((lane & 8) ? 16 : 0));

    float acc[2][8][4];
    #pragma unroll
    for (int mi = 0; mi < 2; ++mi)
        #pragma unroll
        for (int ni = 0; ni < 8; ++ni)
            #pragma unroll
            for (int j = 0; j < 4; ++j) acc[mi][ni][j] = 0.f;

    // gmem mapping
    // A: idx = i*256+tid -> r = idx>>3 (0..127), c4 = idx&7 (float4 along k)
    // B: idx = i*256+tid -> p = (tid&7)+8*i (k-pair 0..15), nq = tid>>3 (0..31)
    const int a_r  = tid >> 3;        // + i*32
    const int a_c4 = tid & 7;
    const int b_p0 = tid & 7;         // + 8*i
    const int b_nq = tid >> 3;

    auto store_tile = [&](int buf, const float4* a4, const float4* be, const float4* bo) {
        #pragma unroll
        for (int i = 0; i < 4; ++i) {
            uint32_t p0 = pack_f16x2(a4[i].x, a4[i].y);
            uint32_t p1 = pack_f16x2(a4[i].z, a4[i].w);
            *reinterpret_cast<uint2*>(&As[buf][a_r + i * 32][a_c4 * 2]) =
                make_uint2(p0, p1);
        }
        #pragma unroll
        for (int i = 0; i < 2; ++i) {
            int p = b_p0 + 8 * i;
            Bs[buf][b_nq * 4 + 0][p] = pack_f16x2(be[i].x, bo[i].x);
            Bs[buf][b_nq * 4 + 1][p] = pack_f16x2(be[i].y, bo[i].y);
            Bs[buf][b_nq * 4 + 2][p] = pack_f16x2(be[i].z, bo[i].z);
            Bs[buf][b_nq * 4 + 3][p] = pack_f16x2(be[i].w, bo[i].w);
        }
    };
    auto load_gmem = [&](int kt, float4* a4, float4* be, float4* bo) {
        int k0 = kt * BK;
        #pragma unroll
        for (int i = 0; i < 4; ++i)
            a4[i] = *reinterpret_cast<const float4*>(
                X + (size_t)(m0 + a_r + i * 32) * DIM + k0 + a_c4 * 4);
        #pragma unroll
        for (int i = 0; i < 2; ++i) {
            const float* bp = Ua + (size_t)(k0 + 2 * (b_p0 + 8 * i)) * OUTD
                              + n0 + b_nq * 4;
            be[i] = *reinterpret_cast<const float4*>(bp);
            bo[i] = *reinterpret_cast<const float4*>(bp + OUTD);
        }
    };

    // ---- preload tile 0
    {
        float4 a4[4], be[2], bo[2];
        load_gmem(0, a4, be, bo);
        store_tile(0, a4, be, bo);
    }
    __syncthreads();

    for (int kt = 0; kt < NKT; ++kt) {
        const int buf = kt & 1;

        // prefetch next tile to registers
        float4 a4[4], be[2], bo[2];
        if (kt < NKT - 1) load_gmem(kt + 1, a4, be, bo);

        const uint32_t Ab = As_base + (uint32_t)buf * (BM * AROW_W * 4) + offA;
        const uint32_t Bb = Bs_base + (uint32_t)buf * (BN * AROW_W * 4) + offB;

        // compute: 2 k16 steps
        #pragma unroll
        for (int ks = 0; ks < 2; ++ks) {
            uint32_t af[2][4];
            uint32_t bf[8][2];
            #pragma unroll
            for (int mi = 0; mi < 2; ++mi)
                ldsm_x4(af[mi][0], af[mi][1], af[mi][2], af[mi][3],
                        Ab + (uint32_t)(mi * 16 * AROW_W * 4 + ks * 32));
            #pragma unroll
            for (int np = 0; np < 4; ++np)
                ldsm_x4(bf[2 * np][0], bf[2 * np][1], bf[2 * np + 1][0],
                        bf[2 * np + 1][1],
                        Bb + (uint32_t)(np * 16 * AROW_W * 4 + ks * 32));
            #pragma unroll
            for (int mi = 0; mi < 2; ++mi)
                #pragma unroll
                for (int ni = 0; ni < 8; ++ni)
                    mma_f16(acc[mi][ni], af[mi], bf[ni]);
        }

        if (kt < NKT - 1)
            store_tile(buf ^ 1, a4, be, bo);
        __syncthreads();
    }

    // Stage Va and WaS rows for this n-chunk
    if (tid < BN) {
        vva[tid] = Va[n0 + tid];
        wss[tid] = g_WaS[b * OUTD + n0 + tid];
    }
    __syncthreads();

    // Epilogue: tanh + Va-dot, reduce per row
    float rowsum[2][2] = {{0.f, 0.f}, {0.f, 0.f}};
    #pragma unroll
    for (int mi = 0; mi < 2; ++mi) {
        #pragma unroll
        for (int ni = 0; ni < 8; ++ni) {
            #pragma unroll
            for (int j = 0; j < 4; ++j) {
                int nl = wn * 64 + ni * 8 + (t4 << 1) + (j & 1);
                float v = acc[mi][ni][j] + wss[nl];
                rowsum[mi][j >> 1] += tanhf(v) * vva[nl];
            }
        }
    }
    #pragma unroll
    for (int mi = 0; mi < 2; ++mi) {
        #pragma unroll
        for (int h = 0; h < 2; ++h) {
            float s = rowsum[mi][h];
            s += __shfl_xor_sync(0xffffffffu, s, 1);
            s += __shfl_xor_sync(0xffffffffu, s, 2);
            if (t4 == 0) {
                int r = wm * 32 + mi * 16 + gid + h * 8;
                sc[wn][r] = s;
            }
        }
    }
    __syncthreads();
    if (tid < BM) {
        g_partial[(size_t)(m0 + tid) * NCHUNKS + blockIdx.x] = sc[0][tid] + sc[1][tid];
    }
}

// ---------------------------------------------------------------------------
// Kernel 3: relu + softmax over timesteps. 64 blocks x 512 threads
// ---------------------------------------------------------------------------
__global__ __launch_bounds__(512) void softmax_kernel()
{
    int bb = blockIdx.x, t = threadIdx.x;
    const float* p = g_partial + ((size_t)bb * TSTEPS + t) * NCHUNKS;
    float s = 0.f;
    #pragma unroll
    for (int i = 0; i < NCHUNKS; ++i) s += p[i];
    s = fmaxf(s, 0.f);

    __shared__ float red[16];
    __shared__ float smax, ssum;

    float m = s;
    #pragma unroll
    for (int o = 16; o; o >>= 1) m = fmaxf(m, __shfl_xor_sync(0xffffffffu, m, o));
    if ((t & 31) == 0) red[t >> 5] = m;
    __syncthreads();
    if (t == 0) {
        float v = red[0];
        #pragma unroll
        for (int i = 1; i < 16; ++i) v = fmaxf(v, red[i]);
        smax = v;
    }
    __syncthreads();

    float e = expf(s - smax);
    float q = e;
    #pragma unroll
    for (int o = 16; o; o >>= 1) q += __shfl_xor_sync(0xffffffffu, q, o);
    if ((t & 31) == 0) red[t >> 5] = q;
    __syncthreads();
    if (t == 0) {
        float v = 0.f;
        #pragma unroll
        for (int i = 0; i < 16; ++i) v += red[i];
        ssum = v;
    }
    __syncthreads();

    g_sm[bb * TSTEPS + t] = e / ssum;
}

// ---------------------------------------------------------------------------
// Kernel 4: context[b,d] = sum_t inputs[b,t,d] * sm[b,t]
// grid (64, 16) x 256: block covers 64 d-cols (float4/thread), 16-way T split
// ---------------------------------------------------------------------------
__global__ __launch_bounds__(256) void context_kernel(
    const float* __restrict__ X, float* __restrict__ out)
{
    int bb = blockIdx.x;
    int d0 = blockIdx.y * 64;
    int q  = threadIdx.x & 15;    // 16 quads -> 64 d
    int tg = threadIdx.x >> 4;    // 16 t-groups of 32

    __shared__ float w[TSTEPS];
    __shared__ float4 part[16][16];
    for (int i = threadIdx.x; i < TSTEPS; i += 256) w[i] = g_sm[bb * TSTEPS + i];
    __syncthreads();

    const float* xp = X + (size_t)bb * TSTEPS * DIM + d0 + q * 4;
    float4 acc = make_float4(0.f, 0.f, 0.f, 0.f);
    int tb = tg * 32;
    #pragma unroll 8
    for (int t = 0; t < 32; ++t) {
        float4 v = *reinterpret_cast<const float4*>(xp + (size_t)(tb + t) * DIM);
        float ww = w[tb + t];
        acc.x = fmaf(v.x, ww, acc.x);
        acc.y = fmaf(v.y, ww, acc.y);
        acc.z = fmaf(v.z, ww, acc.z);
        acc.w = fmaf(v.w, ww, acc.w);
    }
    part[tg][q] = acc;
    __syncthreads();
    if (threadIdx.x < 16) {
        float4 s = make_float4(0.f, 0.f, 0.f, 0.f);
        #pragma unroll
        for (int g = 0; g < 16; ++g) {
            float4 v = part[g][threadIdx.x];
            s.x += v.x; s.y += v.y; s.z += v.z; s.w += v.w;
        }
        *reinterpret_cast<float4*>(out + bb * DIM + d0 + threadIdx.x * 4) = s;
    }
}

// ---------------------------------------------------------------------------
extern "C" void kernel_launch(void* const* d_in, const int* in_sizes, int n_in,
                              void* d_out, int out_size)
{
    const float* inputs = (const float*)d_in[0];
    const float* prev   = (const float*)d_in[1];
    const float* Wa     = (const float*)d_in[2];
    const float* Ua     = (const float*)d_in[3];
    const float* Va     = (const float*)d_in[4];
    const float* Ba     = (const float*)d_in[5];
    float* out = (float*)d_out;

    was_kernel<<<128, 256>>>(prev, Wa, Ba);
    dim3 g2(NCHUNKS, M_TOTAL / BM);   // (8, 256)
    attn_gemm_kernel<<<g2, 256>>>(inputs, Ua, Va);
    softmax_kernel<<<BATCH, TSTEPS>>>();
    context_kernel<<<dim3(BATCH, DIM / 64), 256>>>(inputs, out);
}

// round 5
// speedup vs baseline: 1.4240x; 1.4240x over previous
#include <cuda_runtime.h>
#include <cuda_fp16.h>
#include <cstdint>
#include <cmath>

// Problem constants
#define BATCH 64
#define TSTEPS 512
#define DIM 1024
#define OUTD 1024
#define M_TOTAL (BATCH * TSTEPS)   // 32768
#define NCHUNKS 8                  // N / BN

// Scratch (device globals: no allocations allowed)
__device__ __half g_Xh[(size_t)M_TOTAL * DIM];   // fp16 copy of inputs (64 MB)
__device__ __half g_UhT[(size_t)OUTD * DIM];     // Ua transposed, fp16 [n][k]
__device__ float g_WaS[BATCH * OUTD];            // prev@Wa + Ba
__device__ float g_partial[M_TOTAL * NCHUNKS];   // per-(row, n-chunk) partial Va-dot
__device__ float g_sm[BATCH * TSTEPS];           // softmax weights

__device__ __forceinline__ uint32_t pack_f16x2(float lo, float hi) {
    uint32_t r;
    asm("cvt.rn.f16x2.f32 %0, %1, %2;" : "=r"(r) : "f"(hi), "f"(lo));
    return r;
}
__device__ __forceinline__ void mma_f16(float* c, const uint32_t* a, const uint32_t* b) {
    asm("mma.sync.aligned.m16n8k16.row.col.f32.f16.f16.f32 "
        "{%0,%1,%2,%3}, {%4,%5,%6,%7}, {%8,%9}, {%0,%1,%2,%3};"
        : "+f"(c[0]), "+f"(c[1]), "+f"(c[2]), "+f"(c[3])
        : "r"(a[0]), "r"(a[1]), "r"(a[2]), "r"(a[3]), "r"(b[0]), "r"(b[1]));
}
__device__ __forceinline__ uint32_t smem_u32(const void* p) {
    uint32_t a;
    asm("{ .reg .u64 t; cvta.to.shared.u64 t, %1; cvt.u32.u64 %0, t; }"
        : "=r"(a) : "l"(p));
    return a;
}
__device__ __forceinline__ void cpasync16(uint32_t dst, const void* src) {
    asm volatile("cp.async.cg.shared.global [%0], [%1], 16;"
                 :: "r"(dst), "l"(src) : "memory");
}
__device__ __forceinline__ void cp_commit() {
    asm volatile("cp.async.commit_group;" ::: "memory");
}
__device__ __forceinline__ void cp_wait1() {
    asm volatile("cp.async.wait_group 1;" ::: "memory");
}

// ---------------------------------------------------------------------------
// Kernel 0a: X fp32 -> fp16 (8 elems/thread)
// ---------------------------------------------------------------------------
__global__ __launch_bounds__(256) void prep_x(const float* __restrict__ X)
{
    size_t i = ((size_t)blockIdx.x * 256 + threadIdx.x) * 8;
    float4 a = *reinterpret_cast<const float4*>(X + i);
    float4 b = *reinterpret_cast<const float4*>(X + i + 4);
    uint4 u;
    u.x = pack_f16x2(a.x, a.y);
    u.y = pack_f16x2(a.z, a.w);
    u.z = pack_f16x2(b.x, b.y);
    u.w = pack_f16x2(b.z, b.w);
    *reinterpret_cast<uint4*>(&g_Xh[i]) = u;
}

// ---------------------------------------------------------------------------
// Kernel 0b: Ua [k][n] fp32 -> g_UhT [n][k] fp16 (32x32 tiles)
// ---------------------------------------------------------------------------
__global__ __launch_bounds__(256) void prep_u(const float* __restrict__ Ua)
{
    __shared__ float t[32][33];
    int bx = blockIdx.x * 32, by = blockIdx.y * 32;   // bx: n, by: k
    int tx = threadIdx.x & 31, ty = threadIdx.x >> 5;
    #pragma unroll
    for (int i = 0; i < 32; i += 8)
        t[ty + i][tx] = Ua[(size_t)(by + ty + i) * OUTD + bx + tx];
    __syncthreads();
    #pragma unroll
    for (int i = 0; i < 32; i += 8)
        g_UhT[(size_t)(bx + ty + i) * DIM + by + tx] = __float2half(t[tx][ty + i]);
}

// ---------------------------------------------------------------------------
// Kernel 1: WaS[b,o] = Ba[o] + sum_k prev[b,k] * Wa[k,o]
// ---------------------------------------------------------------------------
__global__ __launch_bounds__(256) void was_kernel(
    const float* __restrict__ prev, const float* __restrict__ Wa,
    const float* __restrict__ Ba)
{
    int o0 = blockIdx.x * 8;
    int oo = threadIdx.x & 7;
    int bq = threadIdx.x >> 3;

    __shared__ float ps[64][33];
    __shared__ float ws[32][9];

    float acc0 = 0.f, acc1 = 0.f;
    for (int k0 = 0; k0 < OUTD; k0 += 32) {
        #pragma unroll
        for (int j = 0; j < 8; ++j) {
            int e = threadIdx.x + j * 256;
            int bb = e >> 5, kk = e & 31;
            ps[bb][kk] = prev[bb * OUTD + k0 + kk];
        }
        {
            int kk = threadIdx.x >> 3, o = threadIdx.x & 7;
            ws[kk][o] = Wa[(size_t)(k0 + kk) * OUTD + o0 + o];
        }
        __syncthreads();
        #pragma unroll
        for (int kk = 0; kk < 32; ++kk) {
            float w = ws[kk][oo];
            acc0 = fmaf(ps[bq * 2 + 0][kk], w, acc0);
            acc1 = fmaf(ps[bq * 2 + 1][kk], w, acc1);
        }
        __syncthreads();
    }
    float bav = Ba[o0 + oo];
    g_WaS[(bq * 2 + 0) * OUTD + o0 + oo] = acc0 + bav;
    g_WaS[(bq * 2 + 1) * OUTD + o0 + oo] = acc1 + bav;
}

// ---------------------------------------------------------------------------
// Kernel 2: fused GEMM  C = Xh @ UhT^T  (fp16 mma, fp32 accum)
// epilogue: partial[m, nchunk] = sum_n Va[n] * tanh(C[m,n] + WaS[b,n])
// BM=128, BN=128, BK=64, 256 threads, 8 warps (4M x 2N), warp tile 32x64.
// 3-stage cp.async pipeline, one __syncthreads per k-tile.
// SMEM rows: 32 u32 words (64 halves) padded to 36 (stride==4 mod 32 ->
// fragment scalar LDS banks 4*gid+t4, all 32 distinct, conflict-free).
// ---------------------------------------------------------------------------
#define BM 128
#define BN 128
#define BK 64
#define NKT (DIM / BK)     // 16
#define ROW_W 36           // u32 words per smem row (144 B, 16B multiple)
#define STG_W (128 * ROW_W)          // words per tile stage
#define STG_B (STG_W * 4)            // 18432 B
#define GEMM_DYN_SMEM (6 * STG_B)    // 3 stages x (A + B) = 110592 B

__global__ __launch_bounds__(256, 2) void attn_gemm_kernel(
    const float* __restrict__ Va)
{
    extern __shared__ __align__(16) uint32_t sm_[];
    uint32_t* As = sm_;                 // [3][128][ROW_W]
    uint32_t* Bs = sm_ + 3 * STG_W;     // [3][128][ROW_W]
    __shared__ float sc[2][BM];
    __shared__ float vva[BN];
    __shared__ float wss[BN];

    const int tid = threadIdx.x;
    const int lane = tid & 31;
    const int wid = tid >> 5;
    const int wm = wid & 3;
    const int wn = wid >> 2;
    const int gid = lane >> 2;
    const int t4  = lane & 3;
    const int n0 = blockIdx.x * BN;
    const int m0 = blockIdx.y * BM;
    const int b  = m0 >> 9;

    const uint32_t As_u = smem_u32(As);
    const uint32_t Bs_u = smem_u32(Bs);

    // cp.async mapping: 1024 16B-chunks per tile (128 rows x 8), 4/thread
    const int c_row = tid >> 1;           // rows: tid/2 (two threads per row)
    const int c_ch0 = (tid & 1) * 4;      // chunks 0-3 or 4-7
    const __half* Xp = g_Xh + (size_t)(m0 + c_row) * DIM + c_ch0 * 8;
    const __half* Up = g_UhT + (size_t)(n0 + c_row) * DIM + c_ch0 * 8;
    const uint32_t a_dst0 = As_u + (uint32_t)(c_row * ROW_W * 4 + c_ch0 * 16);
    const uint32_t b_dst0 = Bs_u + (uint32_t)(c_row * ROW_W * 4 + c_ch0 * 16);

    auto issue_stage = [&](int kt, int s) {
        const __half* xs = Xp + kt * BK;
        const __half* us = Up + kt * BK;
        uint32_t ad = a_dst0 + (uint32_t)s * STG_B;
        uint32_t bd = b_dst0 + (uint32_t)s * STG_B;
        #pragma unroll
        for (int j = 0; j < 4; ++j) cpasync16(ad + j * 16, xs + j * 8);
        #pragma unroll
        for (int j = 0; j < 4; ++j) cpasync16(bd + j * 16, us + j * 8);
    };

    float acc[2][8][4];
    #pragma unroll
    for (int mi = 0; mi < 2; ++mi)
        #pragma unroll
        for (int ni = 0; ni < 8; ++ni)
            #pragma unroll
            for (int j = 0; j < 4; ++j) acc[mi][ni][j] = 0.f;

    // prologue: stages 0,1
    issue_stage(0, 0); cp_commit();
    issue_stage(1, 1); cp_commit();

    int s_cur = 0, s_nxt = 2;
    for (int kt = 0; kt < NKT; ++kt) {
        cp_wait1();
        __syncthreads();

        if (kt + 2 < NKT) issue_stage(kt + 2, s_nxt);
        cp_commit();

        const uint32_t* Ab = As + s_cur * STG_W;
        const uint32_t* Bb = Bs + s_cur * STG_W;

        #pragma unroll
        for (int ks = 0; ks < 4; ++ks) {
            const int w0 = ks * 8 + t4;
            uint32_t af[2][4];
            uint32_t bf[8][2];
            #pragma unroll
            for (int mi = 0; mi < 2; ++mi) {
                int r = wm * 32 + mi * 16 + gid;
                af[mi][0] = Ab[r * ROW_W + w0];
                af[mi][1] = Ab[(r + 8) * ROW_W + w0];
                af[mi][2] = Ab[r * ROW_W + w0 + 4];
                af[mi][3] = Ab[(r + 8) * ROW_W + w0 + 4];
            }
            #pragma unroll
            for (int ni = 0; ni < 8; ++ni) {
                int n = wn * 64 + ni * 8 + gid;
                bf[ni][0] = Bb[n * ROW_W + w0];
                bf[ni][1] = Bb[n * ROW_W + w0 + 4];
            }
            #pragma unroll
            for (int mi = 0; mi < 2; ++mi)
                #pragma unroll
                for (int ni = 0; ni < 8; ++ni)
                    mma_f16(acc[mi][ni], af[mi], bf[ni]);
        }

        s_cur = (s_cur == 2) ? 0 : s_cur + 1;
        s_nxt = (s_nxt == 2) ? 0 : s_nxt + 1;
    }

    // Stage Va and WaS rows for this n-chunk
    if (tid < BN) {
        vva[tid] = Va[n0 + tid];
        wss[tid] = g_WaS[b * OUTD + n0 + tid];
    }
    __syncthreads();

    // Epilogue: tanh + Va-dot, reduce per row
    float rowsum[2][2] = {{0.f, 0.f}, {0.f, 0.f}};
    #pragma unroll
    for (int mi = 0; mi < 2; ++mi) {
        #pragma unroll
        for (int ni = 0; ni < 8; ++ni) {
            #pragma unroll
            for (int j = 0; j < 4; ++j) {
                int nl = wn * 64 + ni * 8 + (t4 << 1) + (j & 1);
                float v = acc[mi][ni][j] + wss[nl];
                rowsum[mi][j >> 1] += tanhf(v) * vva[nl];
            }
        }
    }
    #pragma unroll
    for (int mi = 0; mi < 2; ++mi) {
        #pragma unroll
        for (int h = 0; h < 2; ++h) {
            float s = rowsum[mi][h];
            s += __shfl_xor_sync(0xffffffffu, s, 1);
            s += __shfl_xor_sync(0xffffffffu, s, 2);
            if (t4 == 0) {
                int r = wm * 32 + mi * 16 + gid + h * 8;
                sc[wn][r] = s;
            }
        }
    }
    __syncthreads();
    if (tid < BM) {
        g_partial[(size_t)(m0 + tid) * NCHUNKS + blockIdx.x] = sc[0][tid] + sc[1][tid];
    }
}

// ---------------------------------------------------------------------------
// Kernel 3: relu + softmax over timesteps. 64 blocks x 512 threads
// ---------------------------------------------------------------------------
__global__ __launch_bounds__(512) void softmax_kernel()
{
    int bb = blockIdx.x, t = threadIdx.x;
    const float* p = g_partial + ((size_t)bb * TSTEPS + t) * NCHUNKS;
    float s = 0.f;
    #pragma unroll
    for (int i = 0; i < NCHUNKS; ++i) s += p[i];
    s = fmaxf(s, 0.f);

    __shared__ float red[16];
    __shared__ float smax, ssum;

    float m = s;
    #pragma unroll
    for (int o = 16; o; o >>= 1) m = fmaxf(m, __shfl_xor_sync(0xffffffffu, m, o));
    if ((t & 31) == 0) red[t >> 5] = m;
    __syncthreads();
    if (t == 0) {
        float v = red[0];
        #pragma unroll
        for (int i = 1; i < 16; ++i) v = fmaxf(v, red[i]);
        smax = v;
    }
    __syncthreads();

    float e = expf(s - smax);
    float q = e;
    #pragma unroll
    for (int o = 16; o; o >>= 1) q += __shfl_xor_sync(0xffffffffu, q, o);
    if ((t & 31) == 0) red[t >> 5] = q;
    __syncthreads();
    if (t == 0) {
        float v = 0.f;
        #pragma unroll
        for (int i = 0; i < 16; ++i) v += red[i];
        ssum = v;
    }
    __syncthreads();

    g_sm[bb * TSTEPS + t] = e / ssum;
}

// ---------------------------------------------------------------------------
// Kernel 4: context[b,d] = sum_t Xh[b,t,d] * sm[b,t]   (fp16 X, fp32 accum)
// grid (64, 8) x 256: block covers 128 d (8 halves/thread), 16-way T split
// ---------------------------------------------------------------------------
__global__ __launch_bounds__(256) void context_kernel(float* __restrict__ out)
{
    int bb = blockIdx.x;
    int d0 = blockIdx.y * 128;
    int o  = threadIdx.x & 15;    // 16 octs -> 128 d
    int tg = threadIdx.x >> 4;    // 16 t-groups of 32

    __shared__ float w[TSTEPS];
    __shared__ float part[16][16][8];
    for (int i = threadIdx.x; i < TSTEPS; i += 256) w[i] = g_sm[bb * TSTEPS + i];
    __syncthreads();

    const __half* xp = g_Xh + (size_t)bb * TSTEPS * DIM + d0 + o * 8;
    float a0 = 0.f, a1 = 0.f, a2 = 0.f, a3 = 0.f,
          a4 = 0.f, a5 = 0.f, a6 = 0.f, a7 = 0.f;
    int tb = tg * 32;
    #pragma unroll 4
    for (int t = 0; t < 32; ++t) {
        uint4 v = *reinterpret_cast<const uint4*>(xp + (size_t)(tb + t) * DIM);
        float ww = w[tb + t];
        float2 f;
        f = __half22float2(*reinterpret_cast<__half2*>(&v.x));
        a0 = fmaf(f.x, ww, a0); a1 = fmaf(f.y, ww, a1);
        f = __half22float2(*reinterpret_cast<__half2*>(&v.y));
        a2 = fmaf(f.x, ww, a2); a3 = fmaf(f.y, ww, a3);
        f = __half22float2(*reinterpret_cast<__half2*>(&v.z));
        a4 = fmaf(f.x, ww, a4); a5 = fmaf(f.y, ww, a5);
        f = __half22float2(*reinterpret_cast<__half2*>(&v.w));
        a6 = fmaf(f.x, ww, a6); a7 = fmaf(f.y, ww, a7);
    }
    part[tg][o][0] = a0; part[tg][o][1] = a1;
    part[tg][o][2] = a2; part[tg][o][3] = a3;
    part[tg][o][4] = a4; part[tg][o][5] = a5;
    part[tg][o][6] = a6; part[tg][o][7] = a7;
    __syncthreads();
    if (threadIdx.x < 128) {
        int d = threadIdx.x;
        float s = 0.f;
        #pragma unroll
        for (int g = 0; g < 16; ++g) s += part[g][d >> 3][d & 7];
        out[bb * DIM + d0 + d] = s;
    }
}

// ---------------------------------------------------------------------------
extern "C" void kernel_launch(void* const* d_in, const int* in_sizes, int n_in,
                              void* d_out, int out_size)
{
    const float* inputs = (const float*)d_in[0];
    const float* prev   = (const float*)d_in[1];
    const float* Wa     = (const float*)d_in[2];
    const float* Ua     = (const float*)d_in[3];
    const float* Va     = (const float*)d_in[4];
    const float* Ba     = (const float*)d_in[5];
    float* out = (float*)d_out;

    cudaFuncSetAttribute(attn_gemm_kernel,
                         cudaFuncAttributeMaxDynamicSharedMemorySize,
                         GEMM_DYN_SMEM);

    prep_x<<<M_TOTAL * DIM / (256 * 8), 256>>>(inputs);
    prep_u<<<dim3(32, 32), 256>>>(Ua);
    was_kernel<<<128, 256>>>(prev, Wa, Ba);
    attn_gemm_kernel<<<dim3(NCHUNKS, M_TOTAL / BM), 256, GEMM_DYN_SMEM>>>(Va);
    softmax_kernel<<<BATCH, TSTEPS>>>();
    context_kernel<<<dim3(BATCH, DIM / 128), 256>>>(out);
}

// round 6
// speedup vs baseline: 1.5332x; 1.0767x over previous
#include <cuda_runtime.h>
#include <cuda_fp16.h>
#include <cstdint>
#include <cmath>

// Problem constants
#define BATCH 64
#define TSTEPS 512
#define DIM 1024
#define OUTD 1024
#define M_TOTAL (BATCH * TSTEPS)   // 32768
#define NCHUNKS 8                  // N / BN

// Scratch (device globals: no allocations allowed)
__device__ __half g_Xh[(size_t)M_TOTAL * DIM];   // fp16 copy of inputs (64 MB)
__device__ __half g_UhT[(size_t)OUTD * DIM];     // Ua transposed, fp16 [n][k]
__device__ float g_WaS[BATCH * OUTD];            // prev@Wa + Ba
__device__ float g_partial[M_TOTAL * NCHUNKS];   // per-(row, n-chunk) partial Va-dot
__device__ float g_sm[BATCH * TSTEPS];           // softmax weights

__device__ __forceinline__ uint32_t pack_f16x2(float lo, float hi) {
    uint32_t r;
    asm("cvt.rn.f16x2.f32 %0, %1, %2;" : "=r"(r) : "f"(hi), "f"(lo));
    return r;
}
__device__ __forceinline__ void mma_f16(float* c, const uint32_t* a, const uint32_t* b) {
    asm("mma.sync.aligned.m16n8k16.row.col.f32.f16.f16.f32 "
        "{%0,%1,%2,%3}, {%4,%5,%6,%7}, {%8,%9}, {%0,%1,%2,%3};"
        : "+f"(c[0]), "+f"(c[1]), "+f"(c[2]), "+f"(c[3])
        : "r"(a[0]), "r"(a[1]), "r"(a[2]), "r"(a[3]), "r"(b[0]), "r"(b[1]));
}
__device__ __forceinline__ uint32_t smem_u32(const void* p) {
    uint32_t a;
    asm("{ .reg .u64 t; cvta.to.shared.u64 t, %1; cvt.u32.u64 %0, t; }"
        : "=r"(a) : "l"(p));
    return a;
}
__device__ __forceinline__ void cpasync16(uint32_t dst, const void* src) {
    asm volatile("cp.async.cg.shared.global [%0], [%1], 16;"
                 :: "r"(dst), "l"(src) : "memory");
}
__device__ __forceinline__ void cp_commit() {
    asm volatile("cp.async.commit_group;" ::: "memory");
}
__device__ __forceinline__ void cp_wait1() {
    asm volatile("cp.async.wait_group 1;" ::: "memory");
}

// ---------------------------------------------------------------------------
// Kernel 0a: X fp32 -> fp16 (8 elems/thread)
// ---------------------------------------------------------------------------
__global__ __launch_bounds__(256) void prep_x(const float* __restrict__ X)
{
    size_t i = ((size_t)blockIdx.x * 256 + threadIdx.x) * 8;
    float4 a = *reinterpret_cast<const float4*>(X + i);
    float4 b = *reinterpret_cast<const float4*>(X + i + 4);
    uint4 u;
    u.x = pack_f16x2(a.x, a.y);
    u.y = pack_f16x2(a.z, a.w);
    u.z = pack_f16x2(b.x, b.y);
    u.w = pack_f16x2(b.z, b.w);
    *reinterpret_cast<uint4*>(&g_Xh[i]) = u;
}

// ---------------------------------------------------------------------------
// Kernel 0b: Ua [k][n] fp32 -> g_UhT [n][k] fp16 (32x32 tiles)
// ---------------------------------------------------------------------------
__global__ __launch_bounds__(256) void prep_u(const float* __restrict__ Ua)
{
    __shared__ float t[32][33];
    int bx = blockIdx.x * 32, by = blockIdx.y * 32;   // bx: n, by: k
    int tx = threadIdx.x & 31, ty = threadIdx.x >> 5;
    #pragma unroll
    for (int i = 0; i < 32; i += 8)
        t[ty + i][tx] = Ua[(size_t)(by + ty + i) * OUTD + bx + tx];
    __syncthreads();
    #pragma unroll
    for (int i = 0; i < 32; i += 8)
        g_UhT[(size_t)(bx + ty + i) * DIM + by + tx] = __float2half(t[tx][ty + i]);
}

// ---------------------------------------------------------------------------
// Kernel 1: WaS[b,o] = Ba[o] + sum_k prev[b,k] * Wa[k,o]
// ---------------------------------------------------------------------------
__global__ __launch_bounds__(256) void was_kernel(
    const float* __restrict__ prev, const float* __restrict__ Wa,
    const float* __restrict__ Ba)
{
    int o0 = blockIdx.x * 8;
    int oo = threadIdx.x & 7;
    int bq = threadIdx.x >> 3;

    __shared__ float ps[64][33];
    __shared__ float ws[32][9];

    float acc0 = 0.f, acc1 = 0.f;
    for (int k0 = 0; k0 < OUTD; k0 += 32) {
        #pragma unroll
        for (int j = 0; j < 8; ++j) {
            int e = threadIdx.x + j * 256;
            int bb = e >> 5, kk = e & 31;
            ps[bb][kk] = prev[bb * OUTD + k0 + kk];
        }
        {
            int kk = threadIdx.x >> 3, o = threadIdx.x & 7;
            ws[kk][o] = Wa[(size_t)(k0 + kk) * OUTD + o0 + o];
        }
        __syncthreads();
        #pragma unroll
        for (int kk = 0; kk < 32; ++kk) {
            float w = ws[kk][oo];
            acc0 = fmaf(ps[bq * 2 + 0][kk], w, acc0);
            acc1 = fmaf(ps[bq * 2 + 1][kk], w, acc1);
        }
        __syncthreads();
    }
    float bav = Ba[o0 + oo];
    g_WaS[(bq * 2 + 0) * OUTD + o0 + oo] = acc0 + bav;
    g_WaS[(bq * 2 + 1) * OUTD + o0 + oo] = acc1 + bav;
}

// ---------------------------------------------------------------------------
// Kernel 2: fused GEMM  C = Xh @ UhT^T  (fp16 mma, fp32 accum)
// epilogue: partial[m, nchunk] = sum_n Va[n] * tanh(C[m,n] + WaS[b,n])
// BM=128, BN=128, BK=32, 256 threads, 8 warps (4M x 2N), warp tile 32x64.
// 3-stage cp.async pipeline; 61,440 B dyn smem -> 2 CTAs/SM (the R5 fix).
// SMEM rows: 16 u32 words (32 halves) padded to 20 -> fragment scalar LDS
// banks (20*row + w) all-distinct per warp phase, conflict-free.
// ---------------------------------------------------------------------------
#define BM 128
#define BN 128
#define BK 32
#define NKT (DIM / BK)     // 32
#define ROW_W 20           // u32 words per smem row (80 B, 16B multiple)
#define STG_W (128 * ROW_W)          // words per tile stage (2560)
#define STG_B (STG_W * 4)            // 10240 B
#define GEMM_DYN_SMEM (6 * STG_B)    // 3 stages x (A + B) = 61440 B

__global__ __launch_bounds__(256, 2) void attn_gemm_kernel(
    const float* __restrict__ Va)
{
    extern __shared__ __align__(16) uint32_t sm_[];
    uint32_t* As = sm_;                 // [3][128][ROW_W]
    uint32_t* Bs = sm_ + 3 * STG_W;     // [3][128][ROW_W]
    __shared__ float sc[2][BM];
    __shared__ float vva[BN];
    __shared__ float wss[BN];

    const int tid = threadIdx.x;
    const int lane = tid & 31;
    const int wid = tid >> 5;
    const int wm = wid & 3;
    const int wn = wid >> 2;
    const int gid = lane >> 2;
    const int t4  = lane & 3;
    const int n0 = blockIdx.x * BN;
    const int m0 = blockIdx.y * BM;
    const int b  = m0 >> 9;

    const uint32_t As_u = smem_u32(As);
    const uint32_t Bs_u = smem_u32(Bs);

    // cp.async mapping: 512 16B-chunks per operand tile (128 rows x 4), 2/thread
    const int c_row = tid >> 1;           // 0..127 (two threads per row)
    const int c_ch0 = (tid & 1) * 2;      // chunks 0-1 or 2-3
    const __half* Xp = g_Xh + (size_t)(m0 + c_row) * DIM + c_ch0 * 8;
    const __half* Up = g_UhT + (size_t)(n0 + c_row) * DIM + c_ch0 * 8;
    const uint32_t a_dst0 = As_u + (uint32_t)(c_row * ROW_W * 4 + c_ch0 * 16);
    const uint32_t b_dst0 = Bs_u + (uint32_t)(c_row * ROW_W * 4 + c_ch0 * 16);

    auto issue_stage = [&](int kt, int s) {
        const __half* xs = Xp + kt * BK;
        const __half* us = Up + kt * BK;
        uint32_t ad = a_dst0 + (uint32_t)s * STG_B;
        uint32_t bd = b_dst0 + (uint32_t)s * STG_B;
        #pragma unroll
        for (int j = 0; j < 2; ++j) cpasync16(ad + j * 16, xs + j * 8);
        #pragma unroll
        for (int j = 0; j < 2; ++j) cpasync16(bd + j * 16, us + j * 8);
    };

    float acc[2][8][4];
    #pragma unroll
    for (int mi = 0; mi < 2; ++mi)
        #pragma unroll
        for (int ni = 0; ni < 8; ++ni)
            #pragma unroll
            for (int j = 0; j < 4; ++j) acc[mi][ni][j] = 0.f;

    // prologue: stages 0,1
    issue_stage(0, 0); cp_commit();
    issue_stage(1, 1); cp_commit();

    int s_cur = 0, s_nxt = 2;
    for (int kt = 0; kt < NKT; ++kt) {
        cp_wait1();
        __syncthreads();

        if (kt + 2 < NKT) issue_stage(kt + 2, s_nxt);
        cp_commit();

        const uint32_t* Ab = As + s_cur * STG_W;
        const uint32_t* Bb = Bs + s_cur * STG_W;

        #pragma unroll
        for (int ks = 0; ks < 2; ++ks) {
            const int w0 = ks * 8 + t4;
            uint32_t af[2][4];
            uint32_t bf[8][2];
            #pragma unroll
            for (int mi = 0; mi < 2; ++mi) {
                int r = wm * 32 + mi * 16 + gid;
                af[mi][0] = Ab[r * ROW_W + w0];
                af[mi][1] = Ab[(r + 8) * ROW_W + w0];
                af[mi][2] = Ab[r * ROW_W + w0 + 4];
                af[mi][3] = Ab[(r + 8) * ROW_W + w0 + 4];
            }
            #pragma unroll
            for (int ni = 0; ni < 8; ++ni) {
                int n = wn * 64 + ni * 8 + gid;
                bf[ni][0] = Bb[n * ROW_W + w0];
                bf[ni][1] = Bb[n * ROW_W + w0 + 4];
            }
            #pragma unroll
            for (int mi = 0; mi < 2; ++mi)
                #pragma unroll
                for (int ni = 0; ni < 8; ++ni)
                    mma_f16(acc[mi][ni], af[mi], bf[ni]);
        }

        s_cur = (s_cur == 2) ? 0 : s_cur + 1;
        s_nxt = (s_nxt == 2) ? 0 : s_nxt + 1;
    }

    // Stage Va and WaS rows for this n-chunk
    if (tid < BN) {
        vva[tid] = Va[n0 + tid];
        wss[tid] = g_WaS[b * OUTD + n0 + tid];
    }
    __syncthreads();

    // Epilogue: tanh + Va-dot, reduce per row
    float rowsum[2][2] = {{0.f, 0.f}, {0.f, 0.f}};
    #pragma unroll
    for (int mi = 0; mi < 2; ++mi) {
        #pragma unroll
        for (int ni = 0; ni < 8; ++ni) {
            #pragma unroll
            for (int j = 0; j < 4; ++j) {
                int nl = wn * 64 + ni * 8 + (t4 << 1) + (j & 1);
                float v = acc[mi][ni][j] + wss[nl];
                rowsum[mi][j >> 1] += tanhf(v) * vva[nl];
            }
        }
    }
    #pragma unroll
    for (int mi = 0; mi < 2; ++mi) {
        #pragma unroll
        for (int h = 0; h < 2; ++h) {
            float s = rowsum[mi][h];
            s += __shfl_xor_sync(0xffffffffu, s, 1);
            s += __shfl_xor_sync(0xffffffffu, s, 2);
            if (t4 == 0) {
                int r = wm * 32 + mi * 16 + gid + h * 8;
                sc[wn][r] = s;
            }
        }
    }
    __syncthreads();
    if (tid < BM) {
        g_partial[(size_t)(m0 + tid) * NCHUNKS + blockIdx.x] = sc[0][tid] + sc[1][tid];
    }
}

// ---------------------------------------------------------------------------
// Kernel 3: relu + softmax over timesteps. 64 blocks x 512 threads
// ---------------------------------------------------------------------------
__global__ __launch_bounds__(512) void softmax_kernel()
{
    int bb = blockIdx.x, t = threadIdx.x;
    const float* p = g_partial + ((size_t)bb * TSTEPS + t) * NCHUNKS;
    float s = 0.f;
    #pragma unroll
    for (int i = 0; i < NCHUNKS; ++i) s += p[i];
    s = fmaxf(s, 0.f);

    __shared__ float red[16];
    __shared__ float smax, ssum;

    float m = s;
    #pragma unroll
    for (int o = 16; o; o >>= 1) m = fmaxf(m, __shfl_xor_sync(0xffffffffu, m, o));
    if ((t & 31) == 0) red[t >> 5] = m;
    __syncthreads();
    if (t == 0) {
        float v = red[0];
        #pragma unroll
        for (int i = 1; i < 16; ++i) v = fmaxf(v, red[i]);
        smax = v;
    }
    __syncthreads();

    float e = expf(s - smax);
    float q = e;
    #pragma unroll
    for (int o = 16; o; o >>= 1) q += __shfl_xor_sync(0xffffffffu, q, o);
    if ((t & 31) == 0) red[t >> 5] = q;
    __syncthreads();
    if (t == 0) {
        float v = 0.f;
        #pragma unroll
        for (int i = 0; i < 16; ++i) v += red[i];
        ssum = v;
    }
    __syncthreads();

    g_sm[bb * TSTEPS + t] = e / ssum;
}

// ---------------------------------------------------------------------------
// Kernel 4: context[b,d] = sum_t Xh[b,t,d] * sm[b,t]   (fp16 X, fp32 accum)
// grid (64, 8) x 256: block covers 128 d (8 halves/thread), 16-way T split
// ---------------------------------------------------------------------------
__global__ __launch_bounds__(256) void context_kernel(float* __restrict__ out)
{
    int bb = blockIdx.x;
    int d0 = blockIdx.y * 128;
    int o  = threadIdx.x & 15;    // 16 octs -> 128 d
    int tg = threadIdx.x >> 4;    // 16 t-groups of 32

    __shared__ float w[TSTEPS];
    __shared__ float part[16][16][8];
    for (int i = threadIdx.x; i < TSTEPS; i += 256) w[i] = g_sm[bb * TSTEPS + i];
    __syncthreads();

    const __half* xp = g_Xh + (size_t)bb * TSTEPS * DIM + d0 + o * 8;
    float a0 = 0.f, a1 = 0.f, a2 = 0.f, a3 = 0.f,
          a4 = 0.f, a5 = 0.f, a6 = 0.f, a7 = 0.f;
    int tb = tg * 32;
    #pragma unroll 4
    for (int t = 0; t < 32; ++t) {
        uint4 v = *reinterpret_cast<const uint4*>(xp + (size_t)(tb + t) * DIM);
        float ww = w[tb + t];
        float2 f;
        f = __half22float2(*reinterpret_cast<__half2*>(&v.x));
        a0 = fmaf(f.x, ww, a0); a1 = fmaf(f.y, ww, a1);
        f = __half22float2(*reinterpret_cast<__half2*>(&v.y));
        a2 = fmaf(f.x, ww, a2); a3 = fmaf(f.y, ww, a3);
        f = __half22float2(*reinterpret_cast<__half2*>(&v.z));
        a4 = fmaf(f.x, ww, a4); a5 = fmaf(f.y, ww, a5);
        f = __half22float2(*reinterpret_cast<__half2*>(&v.w));
        a6 = fmaf(f.x, ww, a6); a7 = fmaf(f.y, ww, a7);
    }
    part[tg][o][0] = a0; part[tg][o][1] = a1;
    part[tg][o][2] = a2; part[tg][o][3] = a3;
    part[tg][o][4] = a4; part[tg][o][5] = a5;
    part[tg][o][6] = a6; part[tg][o][7] = a7;
    __syncthreads();
    if (threadIdx.x < 128) {
        int d = threadIdx.x;
        float s = 0.f;
        #pragma unroll
        for (int g = 0; g < 16; ++g) s += part[g][d >> 3][d & 7];
        out[bb * DIM + d0 + d] = s;
    }
}

// ---------------------------------------------------------------------------
extern "C" void kernel_launch(void* const* d_in, const int* in_sizes, int n_in,
                              void* d_out, int out_size)
{
    const float* inputs = (const float*)d_in[0];
    const float* prev   = (const float*)d_in[1];
    const float* Wa     = (const float*)d_in[2];
    const float* Ua     = (const float*)d_in[3];
    const float* Va     = (const float*)d_in[4];
    const float* Ba     = (const float*)d_in[5];
    float* out = (float*)d_out;

    cudaFuncSetAttribute(attn_gemm_kernel,
                         cudaFuncAttributeMaxDynamicSharedMemorySize,
                         GEMM_DYN_SMEM);

    prep_x<<<M_TOTAL * DIM / (256 * 8), 256>>>(inputs);
    prep_u<<<dim3(32, 32), 256>>>(Ua);
    was_kernel<<<128, 256>>>(prev, Wa, Ba);
    attn_gemm_kernel<<<dim3(NCHUNKS, M_TOTAL / BM), 256, GEMM_DYN_SMEM>>>(Va);
    softmax_kernel<<<BATCH, TSTEPS>>>();
    context_kernel<<<dim3(BATCH, DIM / 128), 256>>>(out);
}